// round 2
// baseline (speedup 1.0000x reference)
#include <cuda_runtime.h>

// Problem constants
#define BATCH 4
#define SEQ   2048
#define DMODEL 1024
#define NHEADS 16
#define DHEAD  64
#define MROWS (BATCH*SEQ)   // 8192

// Scratch (allocation-free: __device__ globals)
__device__ float g_q [BATCH*NHEADS*SEQ*DHEAD];   // [B,H,L,dh]
__device__ float g_k [BATCH*NHEADS*SEQ*DHEAD];
__device__ float g_v [BATCH*NHEADS*SEQ*DHEAD];
__device__ float g_ao[MROWS*DMODEL];             // [B*L, D]

// ---------------------------------------------------------------------------
// SGEMM: C = A @ W^T.  A:[M,K] row-major, W:[N,K] row-major.
// M=8192, N=1024, K=1024. Tile 128x128x16, 256 threads, 8x8 per thread
// (split fragments: rows {ty*4..+3, 64+ty*4..+3}, cols same with tx).
// PERMUTE=1: scatter output into [B,H,L,dh] layout for attention.
// ---------------------------------------------------------------------------
template<int PERMUTE>
__global__ void __launch_bounds__(256, 2)
sgemm_nt(const float* __restrict__ A, const float* __restrict__ W,
         float* __restrict__ C)
{
    const int K = DMODEL;
    __shared__ float As[16 * 132];   // [k][m] transposed, padded stride
    __shared__ float Ws[16 * 132];   // [k][n] transposed, padded stride

    const int tid = threadIdx.x;
    const int m0 = blockIdx.y * 128;
    const int n0 = blockIdx.x * 128;
    const int tx = tid & 15;
    const int ty = tid >> 4;

    float acc[8][8];
    #pragma unroll
    for (int i = 0; i < 8; i++)
        #pragma unroll
        for (int j = 0; j < 8; j++) acc[i][j] = 0.0f;

    for (int k0 = 0; k0 < K; k0 += 16) {
        // Load A and W tiles (each 128 rows x 16 cols = 512 float4)
        #pragma unroll
        for (int it = 0; it < 2; it++) {
            int idx = tid + it * 256;      // float4 index 0..511
            int row = idx >> 2;            // 0..127
            int cg  = idx & 3;             // 0..3 (4 floats each)
            float4 va = *reinterpret_cast<const float4*>(
                &A[(size_t)(m0 + row) * K + k0 + cg * 4]);
            As[(cg*4+0)*132 + row] = va.x;
            As[(cg*4+1)*132 + row] = va.y;
            As[(cg*4+2)*132 + row] = va.z;
            As[(cg*4+3)*132 + row] = va.w;
            float4 vw = *reinterpret_cast<const float4*>(
                &W[(size_t)(n0 + row) * K + k0 + cg * 4]);
            Ws[(cg*4+0)*132 + row] = vw.x;
            Ws[(cg*4+1)*132 + row] = vw.y;
            Ws[(cg*4+2)*132 + row] = vw.z;
            Ws[(cg*4+3)*132 + row] = vw.w;
        }
        __syncthreads();

        #pragma unroll
        for (int kk = 0; kk < 16; kk++) {
            float a[8], b[8];
            float4 a0 = *reinterpret_cast<const float4*>(&As[kk*132 + ty*4]);
            float4 a1 = *reinterpret_cast<const float4*>(&As[kk*132 + 64 + ty*4]);
            float4 b0 = *reinterpret_cast<const float4*>(&Ws[kk*132 + tx*4]);
            float4 b1 = *reinterpret_cast<const float4*>(&Ws[kk*132 + 64 + tx*4]);
            a[0]=a0.x; a[1]=a0.y; a[2]=a0.z; a[3]=a0.w;
            a[4]=a1.x; a[5]=a1.y; a[6]=a1.z; a[7]=a1.w;
            b[0]=b0.x; b[1]=b0.y; b[2]=b0.z; b[3]=b0.w;
            b[4]=b1.x; b[5]=b1.y; b[6]=b1.z; b[7]=b1.w;
            #pragma unroll
            for (int i = 0; i < 8; i++)
                #pragma unroll
                for (int j = 0; j < 8; j++)
                    acc[i][j] += a[i] * b[j];
        }
        __syncthreads();
    }

    // Epilogue
    #pragma unroll
    for (int i = 0; i < 8; i++) {
        int m = m0 + ((i < 4) ? (ty*4 + i) : (64 + ty*4 + i - 4));
        float4 v0 = make_float4(acc[i][0], acc[i][1], acc[i][2], acc[i][3]);
        float4 v1 = make_float4(acc[i][4], acc[i][5], acc[i][6], acc[i][7]);
        int nc0 = n0 + tx*4;
        int nc1 = n0 + 64 + tx*4;
        if (PERMUTE) {
            int b = m >> 11;           // / SEQ
            int l = m & (SEQ - 1);
            int h0 = nc0 >> 6, d0 = nc0 & 63;
            int h1 = nc1 >> 6, d1 = nc1 & 63;
            *reinterpret_cast<float4*>(
                &C[(((size_t)(b*NHEADS + h0)) * SEQ + l) * DHEAD + d0]) = v0;
            *reinterpret_cast<float4*>(
                &C[(((size_t)(b*NHEADS + h1)) * SEQ + l) * DHEAD + d1]) = v1;
        } else {
            *reinterpret_cast<float4*>(&C[(size_t)m * DMODEL + nc0]) = v0;
            *reinterpret_cast<float4*>(&C[(size_t)m * DMODEL + nc1]) = v1;
        }
    }
}

// ---------------------------------------------------------------------------
// Flash attention, causal. One CTA = one (b,h) x 64-query block.
// BQ=64, BK=32, dh=64, 256 threads. Thread (tx 0..7, ty 0..31):
//   S tile: rows ty*2..+2, cols tx*4..+4
//   O tile: rows ty*2..+2, dims tx*8..+8
// ---------------------------------------------------------------------------
__global__ void __launch_bounds__(256, 2)
attn_kernel(const float* __restrict__ gq, const float* __restrict__ gk,
            const float* __restrict__ gv, float* __restrict__ ao)
{
    __shared__ float Qs [64 * 64];   // [q][d], pre-scaled
    __shared__ float Kst[64 * 32];   // [d][key]
    __shared__ float Vs [32 * 64];   // [key][d]
    __shared__ float Ps [64 * 36];   // [q][key], padded stride 36

    const int tid = threadIdx.x;
    const int bh  = blockIdx.y;
    const int qb  = blockIdx.x;
    const int q0  = qb * 64;
    const float scale = 0.125f;      // 1/sqrt(64)

    // Load Q block (contiguous 4096 floats), apply scale
    {
        const float4* qbase = reinterpret_cast<const float4*>(
            gq + ((size_t)bh * SEQ + q0) * DHEAD);
        float4* dst = reinterpret_cast<float4*>(Qs);
        #pragma unroll
        for (int it = 0; it < 4; it++) {
            int idx = tid + it * 256;
            float4 v = qbase[idx];
            v.x *= scale; v.y *= scale; v.z *= scale; v.w *= scale;
            dst[idx] = v;
        }
    }

    const int tx = tid & 7;
    const int ty = tid >> 3;

    float m_i[2] = {-1e30f, -1e30f};
    float l_i[2] = {0.0f, 0.0f};
    float o[2][8];
    #pragma unroll
    for (int r = 0; r < 2; r++)
        #pragma unroll
        for (int j = 0; j < 8; j++) o[r][j] = 0.0f;

    const int nkb = 2*qb + 2;   // key blocks up to and including diagonal
    for (int kb = 0; kb < nkb; kb++) {
        const int k0 = kb * 32;
        // Load K (transposed) and V tiles: 512 float4 each source
        {
            const float4* kbase = reinterpret_cast<const float4*>(
                gk + ((size_t)bh * SEQ + k0) * DHEAD);
            const float4* vbase = reinterpret_cast<const float4*>(
                gv + ((size_t)bh * SEQ + k0) * DHEAD);
            float4* vdst = reinterpret_cast<float4*>(Vs);
            #pragma unroll
            for (int it = 0; it < 2; it++) {
                int idx = tid + it * 256;   // 0..511
                int kc = idx >> 4;          // key 0..31
                int dg = idx & 15;          // d-group
                float4 vk = kbase[idx];
                Kst[(dg*4+0)*32 + kc] = vk.x;
                Kst[(dg*4+1)*32 + kc] = vk.y;
                Kst[(dg*4+2)*32 + kc] = vk.z;
                Kst[(dg*4+3)*32 + kc] = vk.w;
                vdst[idx] = vbase[idx];
            }
        }
        __syncthreads();

        // S = Q @ K^T  (64x32, 2x4 per thread)
        float s[2][4];
        #pragma unroll
        for (int r = 0; r < 2; r++)
            #pragma unroll
            for (int c = 0; c < 4; c++) s[r][c] = 0.0f;

        #pragma unroll 4
        for (int kk = 0; kk < 64; kk += 4) {
            float4 qa = *reinterpret_cast<const float4*>(&Qs[(ty*2+0)*64 + kk]);
            float4 qb4 = *reinterpret_cast<const float4*>(&Qs[(ty*2+1)*64 + kk]);
            float qav[4] = {qa.x, qa.y, qa.z, qa.w};
            float qbv[4] = {qb4.x, qb4.y, qb4.z, qb4.w};
            #pragma unroll
            for (int u = 0; u < 4; u++) {
                float4 kv = *reinterpret_cast<const float4*>(&Kst[(kk+u)*32 + tx*4]);
                s[0][0] += qav[u]*kv.x; s[0][1] += qav[u]*kv.y;
                s[0][2] += qav[u]*kv.z; s[0][3] += qav[u]*kv.w;
                s[1][0] += qbv[u]*kv.x; s[1][1] += qbv[u]*kv.y;
                s[1][2] += qbv[u]*kv.z; s[1][3] += qbv[u]*kv.w;
            }
        }

        // Causal mask
        #pragma unroll
        for (int r = 0; r < 2; r++) {
            int qg = q0 + ty*2 + r;
            #pragma unroll
            for (int c = 0; c < 4; c++) {
                int kg = k0 + tx*4 + c;
                if (kg > qg) s[r][c] = -1e30f;
            }
        }

        // Online softmax update (row reduce over 8 tx lanes)
        #pragma unroll
        for (int r = 0; r < 2; r++) {
            float mx = fmaxf(fmaxf(s[r][0], s[r][1]), fmaxf(s[r][2], s[r][3]));
            #pragma unroll
            for (int off = 1; off < 8; off <<= 1)
                mx = fmaxf(mx, __shfl_xor_sync(0xffffffffu, mx, off));
            float newm = fmaxf(m_i[r], mx);
            float p0 = __expf(s[r][0] - newm);
            float p1 = __expf(s[r][1] - newm);
            float p2 = __expf(s[r][2] - newm);
            float p3 = __expf(s[r][3] - newm);
            float rs = (p0 + p1) + (p2 + p3);
            #pragma unroll
            for (int off = 1; off < 8; off <<= 1)
                rs += __shfl_xor_sync(0xffffffffu, rs, off);
            float corr = __expf(m_i[r] - newm);
            l_i[r] = l_i[r] * corr + rs;
            m_i[r] = newm;
            #pragma unroll
            for (int j = 0; j < 8; j++) o[r][j] *= corr;
            int prow = (ty*2 + r) * 36 + tx*4;
            Ps[prow+0] = p0; Ps[prow+1] = p1; Ps[prow+2] = p2; Ps[prow+3] = p3;
        }
        __syncthreads();

        // O += P @ V  (64x64, 2x8 per thread)
        #pragma unroll 4
        for (int kc = 0; kc < 32; kc += 4) {
            float4 pa = *reinterpret_cast<const float4*>(&Ps[(ty*2+0)*36 + kc]);
            float4 pb = *reinterpret_cast<const float4*>(&Ps[(ty*2+1)*36 + kc]);
            float pav[4] = {pa.x, pa.y, pa.z, pa.w};
            float pbv[4] = {pb.x, pb.y, pb.z, pb.w};
            #pragma unroll
            for (int u = 0; u < 4; u++) {
                float4 v0 = *reinterpret_cast<const float4*>(&Vs[(kc+u)*64 + tx*8]);
                float4 v1 = *reinterpret_cast<const float4*>(&Vs[(kc+u)*64 + tx*8 + 4]);
                o[0][0] += pav[u]*v0.x; o[0][1] += pav[u]*v0.y;
                o[0][2] += pav[u]*v0.z; o[0][3] += pav[u]*v0.w;
                o[0][4] += pav[u]*v1.x; o[0][5] += pav[u]*v1.y;
                o[0][6] += pav[u]*v1.z; o[0][7] += pav[u]*v1.w;
                o[1][0] += pbv[u]*v0.x; o[1][1] += pbv[u]*v0.y;
                o[1][2] += pbv[u]*v0.z; o[1][3] += pbv[u]*v0.w;
                o[1][4] += pbv[u]*v1.x; o[1][5] += pbv[u]*v1.y;
                o[1][6] += pbv[u]*v1.z; o[1][7] += pbv[u]*v1.w;
            }
        }
        __syncthreads();
    }

    // Normalize and write to [B*L, D] layout (col = h*64 + d)
    const int b = bh >> 4;
    const int h = bh & 15;
    #pragma unroll
    for (int r = 0; r < 2; r++) {
        float inv = 1.0f / l_i[r];
        int row = q0 + ty*2 + r;
        float* dst = ao + ((size_t)(b * SEQ + row)) * DMODEL + h * DHEAD + tx*8;
        float4 w0 = make_float4(o[r][0]*inv, o[r][1]*inv, o[r][2]*inv, o[r][3]*inv);
        float4 w1 = make_float4(o[r][4]*inv, o[r][5]*inv, o[r][6]*inv, o[r][7]*inv);
        *reinterpret_cast<float4*>(dst)     = w0;
        *reinterpret_cast<float4*>(dst + 4) = w1;
    }
}

// ---------------------------------------------------------------------------
extern "C" void kernel_launch(void* const* d_in, const int* in_sizes, int n_in,
                              void* d_out, int out_size)
{
    const float* x  = (const float*)d_in[0];
    const float* Wq = (const float*)d_in[1];
    const float* Wk = (const float*)d_in[2];
    const float* Wv = (const float*)d_in[3];
    const float* Wo = (const float*)d_in[4];
    float* out = (float*)d_out;

    float *qp, *kp, *vp, *aop;
    cudaGetSymbolAddress((void**)&qp,  g_q);
    cudaGetSymbolAddress((void**)&kp,  g_k);
    cudaGetSymbolAddress((void**)&vp,  g_v);
    cudaGetSymbolAddress((void**)&aop, g_ao);

    dim3 gemm_grid(DMODEL / 128, MROWS / 128);   // (8, 64)
    sgemm_nt<1><<<gemm_grid, 256>>>(x, Wq, qp);
    sgemm_nt<1><<<gemm_grid, 256>>>(x, Wk, kp);
    sgemm_nt<1><<<gemm_grid, 256>>>(x, Wv, vp);

    dim3 attn_grid(SEQ / 64, BATCH * NHEADS);    // (32, 64)
    attn_kernel<<<attn_grid, 256>>>(qp, kp, vp, aop);

    sgemm_nt<0><<<gemm_grid, 256>>>(aop, Wo, out);
}

// round 3
// speedup vs baseline: 4.2708x; 4.2708x over previous
#include <cuda_runtime.h>
#include <cstdint>

// Problem constants
#define BATCH 4
#define SEQ   2048
#define DMODEL 1024
#define NHEADS 16
#define DHEAD  64
#define MROWS (BATCH*SEQ)   // 8192

// Scratch (allocation-free: __device__ globals)
__device__ float g_q [BATCH*NHEADS*SEQ*DHEAD];   // [B,H,L,dh]
__device__ float g_k [BATCH*NHEADS*SEQ*DHEAD];
__device__ float g_v [BATCH*NHEADS*SEQ*DHEAD];
__device__ float g_ao[MROWS*DMODEL];             // [B*L, D]

__device__ __forceinline__ uint32_t to_tf32(float f) {
    uint32_t r;
    asm("cvt.rna.tf32.f32 %0, %1;" : "=r"(r) : "f"(f));
    return r;
}
__device__ __forceinline__ float tf32f(float f) {
    return __uint_as_float(to_tf32(f));
}

#define LDSM4(r0,r1,r2,r3,addr) \
    asm volatile("ldmatrix.sync.aligned.m8n8.x4.shared.b16 {%0,%1,%2,%3}, [%4];" \
        : "=r"(r0),"=r"(r1),"=r"(r2),"=r"(r3) : "r"(addr))

#define MMA_TF32(c,a,b0,b1) \
    asm volatile("mma.sync.aligned.m16n8k8.row.col.f32.tf32.tf32.f32 " \
        "{%0,%1,%2,%3},{%4,%5,%6,%7},{%8,%9},{%0,%1,%2,%3};" \
        : "+f"(c[0]),"+f"(c[1]),"+f"(c[2]),"+f"(c[3]) \
        : "r"(a[0]),"r"(a[1]),"r"(a[2]),"r"(a[3]),"r"(b0),"r"(b1))

// ---------------------------------------------------------------------------
// tf32 GEMM: C = A @ W^T.  A:[M,K] row-major, W:[N,K] row-major.
// CTA tile 128x128x32, 256 threads (8 warps, 2x4), warp tile 64x32.
// PERMUTE=1: scatter output into [B,H,L,dh].
// ---------------------------------------------------------------------------
template<int PERMUTE>
__global__ void __launch_bounds__(256, 2)
gemm_tf32(const float* __restrict__ A, const float* __restrict__ W,
          float* __restrict__ C)
{
    const int K = DMODEL;
    __shared__ float As[128 * 36];   // [m][k], stride 36 (conflict-free LDSM)
    __shared__ float Ws[128 * 36];   // [n][k], stride 36

    const int tid  = threadIdx.x;
    const int lane = tid & 31;
    const int wid  = tid >> 5;
    const int m0 = blockIdx.y * 128;
    const int n0 = blockIdx.x * 128;
    const int wm = (wid & 1) * 64;     // warp m offset in tile
    const int wn = (wid >> 1) * 32;    // warp n offset in tile

    float c[4][4][4];
    #pragma unroll
    for (int i = 0; i < 4; i++)
        #pragma unroll
        for (int j = 0; j < 4; j++)
            #pragma unroll
            for (int r = 0; r < 4; r++) c[i][j][r] = 0.0f;

    // Per-thread LDSM base addresses (shared address space)
    uint32_t as_base = (uint32_t)__cvta_generic_to_shared(As);
    uint32_t ws_base = (uint32_t)__cvta_generic_to_shared(Ws);
    uint32_t a_addr[4], b_addr[2];
    #pragma unroll
    for (int i = 0; i < 4; i++)
        a_addr[i] = as_base + ((wm + i*16 + (lane & 15)) * 36 + (lane >> 4) * 4) * 4;
    #pragma unroll
    for (int p = 0; p < 2; p++)
        b_addr[p] = ws_base + ((wn + p*16 + ((lane >> 4) & 1) * 8 + (lane & 7)) * 36
                               + ((lane >> 3) & 1) * 4) * 4;

    for (int k0 = 0; k0 < K; k0 += 32) {
        // Load A and W tiles: each 128 rows x 32 cols = 1024 float4 / tile
        #pragma unroll
        for (int it = 0; it < 4; it++) {
            int idx = tid + it * 256;     // 0..1023
            int row = idx >> 3;           // 0..127
            int cg  = idx & 7;            // 0..7
            float4 va = *reinterpret_cast<const float4*>(
                &A[(size_t)(m0 + row) * K + k0 + cg * 4]);
            float* ad = &As[row * 36 + cg * 4];
            ad[0] = tf32f(va.x); ad[1] = tf32f(va.y);
            ad[2] = tf32f(va.z); ad[3] = tf32f(va.w);
            float4 vw = *reinterpret_cast<const float4*>(
                &W[(size_t)(n0 + row) * K + k0 + cg * 4]);
            float* wd = &Ws[row * 36 + cg * 4];
            wd[0] = tf32f(vw.x); wd[1] = tf32f(vw.y);
            wd[2] = tf32f(vw.z); wd[3] = tf32f(vw.w);
        }
        __syncthreads();

        #pragma unroll
        for (int s = 0; s < 4; s++) {
            uint32_t a[4][4], bb[2][4];
            #pragma unroll
            for (int i = 0; i < 4; i++)
                LDSM4(a[i][0], a[i][1], a[i][2], a[i][3], a_addr[i] + s * 32);
            #pragma unroll
            for (int p = 0; p < 2; p++)
                LDSM4(bb[p][0], bb[p][1], bb[p][2], bb[p][3], b_addr[p] + s * 32);
            #pragma unroll
            for (int i = 0; i < 4; i++) {
                MMA_TF32(c[i][0], a[i], bb[0][0], bb[0][1]);
                MMA_TF32(c[i][1], a[i], bb[0][2], bb[0][3]);
                MMA_TF32(c[i][2], a[i], bb[1][0], bb[1][1]);
                MMA_TF32(c[i][3], a[i], bb[1][2], bb[1][3]);
            }
        }
        __syncthreads();
    }

    // Epilogue: c[i][j] regs {c0,c1}=(row, col 2t,2t+1), {c2,c3}=(row+8, ...)
    const int gq = lane >> 2;        // 0..7
    const int tq = lane & 3;         // 0..3
    #pragma unroll
    for (int i = 0; i < 4; i++) {
        #pragma unroll
        for (int j = 0; j < 4; j++) {
            int col = n0 + wn + j*8 + tq*2;
            #pragma unroll
            for (int t = 0; t < 2; t++) {
                int row = m0 + wm + i*16 + gq + t*8;
                float2 v = make_float2(c[i][j][2*t], c[i][j][2*t+1]);
                if (PERMUTE) {
                    int b = row >> 11, l = row & (SEQ - 1);
                    int h = col >> 6, d = col & 63;
                    *reinterpret_cast<float2*>(
                        &C[(((size_t)(b*NHEADS + h)) * SEQ + l) * DHEAD + d]) = v;
                } else {
                    *reinterpret_cast<float2*>(&C[(size_t)row * DMODEL + col]) = v;
                }
            }
        }
    }
}

// ---------------------------------------------------------------------------
// Flash attention with tf32 mma. CTA = 128 queries x one (b,h).
// 8 warps, each warp owns 16 q rows. Key blocks of 64. dh = 64.
// Dynamic smem: Qs[128][68], Ks[64][68], Vt[64][68] (transposed), Ps[128][68].
// ---------------------------------------------------------------------------
#define QS_OFF 0
#define KS_OFF 8704
#define VT_OFF 13056
#define PS_OFF 17408
#define ATTN_SMEM_FLOATS 26112
#define ATTN_SMEM_BYTES  (ATTN_SMEM_FLOATS*4)

__global__ void __launch_bounds__(256)
attn_tf32(const float* __restrict__ gq, const float* __restrict__ gk,
          const float* __restrict__ gv, float* __restrict__ ao)
{
    extern __shared__ float sm[];
    float* Qs = sm + QS_OFF;
    float* Ks = sm + KS_OFF;
    float* Vt = sm + VT_OFF;
    float* Ps = sm + PS_OFF;

    const int tid  = threadIdx.x;
    const int lane = tid & 31;
    const int wid  = tid >> 5;
    const int bh = blockIdx.y;
    const int q0 = blockIdx.x * 128;
    const float scale = 0.125f;

    // Load + scale + tf32-round Q block: 128x64 = 2048 float4
    {
        const float4* qbase = reinterpret_cast<const float4*>(
            gq + ((size_t)bh * SEQ + q0) * DHEAD);
        #pragma unroll
        for (int it = 0; it < 8; it++) {
            int idx = tid + it * 256;
            int row = idx >> 4, cg = idx & 15;
            float4 v = qbase[idx];
            float* d = &Qs[row * 68 + cg * 4];
            d[0] = tf32f(v.x * scale); d[1] = tf32f(v.y * scale);
            d[2] = tf32f(v.z * scale); d[3] = tf32f(v.w * scale);
        }
    }

    // LDSM base addresses
    uint32_t qs_b = (uint32_t)__cvta_generic_to_shared(Qs);
    uint32_t ks_b = (uint32_t)__cvta_generic_to_shared(Ks);
    uint32_t vt_b = (uint32_t)__cvta_generic_to_shared(Vt);
    uint32_t ps_b = (uint32_t)__cvta_generic_to_shared(Ps);
    uint32_t qa_addr = qs_b + ((wid*16 + (lane & 15)) * 68 + (lane >> 4) * 4) * 4;
    uint32_t pa_addr = ps_b + ((wid*16 + (lane & 15)) * 68 + (lane >> 4) * 4) * 4;
    uint32_t kb_addr[4], vb_addr[4];
    #pragma unroll
    for (int p = 0; p < 4; p++) {
        uint32_t roff = (p*16 + ((lane >> 4) & 1) * 8 + (lane & 7)) * 68
                        + ((lane >> 3) & 1) * 4;
        kb_addr[p] = ks_b + roff * 4;
        vb_addr[p] = vt_b + roff * 4;
    }

    float m_i[2] = {-1e30f, -1e30f};
    float l_i[2] = {0.0f, 0.0f};
    float o[8][4];
    #pragma unroll
    for (int j = 0; j < 8; j++)
        #pragma unroll
        for (int r = 0; r < 4; r++) o[j][r] = 0.0f;

    const int gq0 = lane >> 2;   // row-in-16 base
    const int tq  = lane & 3;

    const int nkb = (q0 + 128) / 64;
    for (int kb = 0; kb < nkb; kb++) {
        const int k0 = kb * 64;
        __syncthreads();   // protect smem reuse (also orders Q-load on iter 0)

        // Load K block [64][64] coalesced; V block transposed into Vt[d][key]
        {
            const float4* kbase = reinterpret_cast<const float4*>(
                gk + ((size_t)bh * SEQ + k0) * DHEAD);
            const float4* vbase = reinterpret_cast<const float4*>(
                gv + ((size_t)bh * SEQ + k0) * DHEAD);
            #pragma unroll
            for (int it = 0; it < 4; it++) {
                int idx = tid + it * 256;      // 0..1023
                {
                    int row = idx >> 4, cg = idx & 15;
                    float4 v = kbase[idx];
                    float* d = &Ks[row * 68 + cg * 4];
                    d[0] = tf32f(v.x); d[1] = tf32f(v.y);
                    d[2] = tf32f(v.z); d[3] = tf32f(v.w);
                }
                {
                    int r = idx & 63, cg = idx >> 6;   // cg 0..15
                    float4 v = vbase[r * 16 + cg];
                    Vt[(cg*4+0) * 68 + r] = tf32f(v.x);
                    Vt[(cg*4+1) * 68 + r] = tf32f(v.y);
                    Vt[(cg*4+2) * 68 + r] = tf32f(v.z);
                    Vt[(cg*4+3) * 68 + r] = tf32f(v.w);
                }
            }
        }
        __syncthreads();

        // S = Q @ K^T : warp m16 x n64 x k64
        float sf[8][4];
        #pragma unroll
        for (int j = 0; j < 8; j++)
            #pragma unroll
            for (int r = 0; r < 4; r++) sf[j][r] = 0.0f;

        #pragma unroll
        for (int s = 0; s < 8; s++) {
            uint32_t a[4], bb[4][4];
            LDSM4(a[0], a[1], a[2], a[3], qa_addr + s * 32);
            #pragma unroll
            for (int p = 0; p < 4; p++)
                LDSM4(bb[p][0], bb[p][1], bb[p][2], bb[p][3], kb_addr[p] + s * 32);
            #pragma unroll
            for (int p = 0; p < 4; p++) {
                MMA_TF32(sf[2*p],   a, bb[p][0], bb[p][1]);
                MMA_TF32(sf[2*p+1], a, bb[p][2], bb[p][3]);
            }
        }

        // Causal mask (only near diagonal)
        if (k0 + 63 > q0 + wid*16) {
            #pragma unroll
            for (int t = 0; t < 2; t++) {
                int qg = q0 + wid*16 + gq0 + t*8;
                #pragma unroll
                for (int j = 0; j < 8; j++) {
                    int kg = k0 + j*8 + tq*2;
                    if (kg   > qg) sf[j][2*t]   = -1e30f;
                    if (kg+1 > qg) sf[j][2*t+1] = -1e30f;
                }
            }
        }

        // Online softmax per row; write P (tf32) to warp-private Ps rows
        #pragma unroll
        for (int t = 0; t < 2; t++) {
            float mx = -1e30f;
            #pragma unroll
            for (int j = 0; j < 8; j++)
                mx = fmaxf(mx, fmaxf(sf[j][2*t], sf[j][2*t+1]));
            mx = fmaxf(mx, __shfl_xor_sync(0xffffffffu, mx, 1));
            mx = fmaxf(mx, __shfl_xor_sync(0xffffffffu, mx, 2));
            float newm = fmaxf(m_i[t], mx);
            float corr = __expf(m_i[t] - newm);
            float rs = 0.0f;
            int prow = (wid*16 + gq0 + t*8) * 68 + tq*2;
            #pragma unroll
            for (int j = 0; j < 8; j++) {
                float p0 = __expf(sf[j][2*t]   - newm);
                float p1 = __expf(sf[j][2*t+1] - newm);
                rs += p0 + p1;
                *reinterpret_cast<float2*>(&Ps[prow + j*8]) =
                    make_float2(tf32f(p0), tf32f(p1));
            }
            rs += __shfl_xor_sync(0xffffffffu, rs, 1);
            rs += __shfl_xor_sync(0xffffffffu, rs, 2);
            l_i[t] = l_i[t] * corr + rs;
            m_i[t] = newm;
            #pragma unroll
            for (int j = 0; j < 8; j++) {
                o[j][2*t]   *= corr;
                o[j][2*t+1] *= corr;
            }
        }
        __syncwarp();

        // O += P @ V : warp m16(q) x n64(d) x k64(keys)
        #pragma unroll
        for (int s = 0; s < 8; s++) {
            uint32_t a[4], bb[4][4];
            LDSM4(a[0], a[1], a[2], a[3], pa_addr + s * 32);
            #pragma unroll
            for (int p = 0; p < 4; p++)
                LDSM4(bb[p][0], bb[p][1], bb[p][2], bb[p][3], vb_addr[p] + s * 32);
            #pragma unroll
            for (int p = 0; p < 4; p++) {
                MMA_TF32(o[2*p],   a, bb[p][0], bb[p][1]);
                MMA_TF32(o[2*p+1], a, bb[p][2], bb[p][3]);
            }
        }
    }

    // Normalize and write to [B*L, D] (col = h*64 + d)
    const int b = bh >> 4;
    const int h = bh & 15;
    #pragma unroll
    for (int t = 0; t < 2; t++) {
        float inv = 1.0f / l_i[t];
        int row = q0 + wid*16 + gq0 + t*8;
        float* dst = ao + ((size_t)(b * SEQ + row)) * DMODEL + h * DHEAD + tq*2;
        #pragma unroll
        for (int j = 0; j < 8; j++)
            *reinterpret_cast<float2*>(dst + j*8) =
                make_float2(o[j][2*t] * inv, o[j][2*t+1] * inv);
    }
}

// ---------------------------------------------------------------------------
extern "C" void kernel_launch(void* const* d_in, const int* in_sizes, int n_in,
                              void* d_out, int out_size)
{
    const float* x  = (const float*)d_in[0];
    const float* Wq = (const float*)d_in[1];
    const float* Wk = (const float*)d_in[2];
    const float* Wv = (const float*)d_in[3];
    const float* Wo = (const float*)d_in[4];
    float* out = (float*)d_out;

    float *qp, *kp, *vp, *aop;
    cudaGetSymbolAddress((void**)&qp,  g_q);
    cudaGetSymbolAddress((void**)&kp,  g_k);
    cudaGetSymbolAddress((void**)&vp,  g_v);
    cudaGetSymbolAddress((void**)&aop, g_ao);

    cudaFuncSetAttribute(attn_tf32,
        cudaFuncAttributeMaxDynamicSharedMemorySize, ATTN_SMEM_BYTES);

    dim3 gemm_grid(DMODEL / 128, MROWS / 128);   // (8, 64)
    gemm_tf32<1><<<gemm_grid, 256>>>(x, Wq, qp);
    gemm_tf32<1><<<gemm_grid, 256>>>(x, Wk, kp);
    gemm_tf32<1><<<gemm_grid, 256>>>(x, Wv, vp);

    dim3 attn_grid(SEQ / 128, BATCH * NHEADS);   // (16, 64)
    attn_tf32<<<attn_grid, 256, ATTN_SMEM_BYTES>>>(qp, kp, vp, aop);

    gemm_tf32<0><<<gemm_grid, 256>>>(aop, Wo, out);
}

// round 4
// speedup vs baseline: 4.8708x; 1.1405x over previous
#include <cuda_runtime.h>
#include <cstdint>

// Problem constants
#define BATCH 4
#define SEQ   2048
#define DMODEL 1024
#define NHEADS 16
#define DHEAD  64
#define MROWS (BATCH*SEQ)   // 8192

// Scratch (allocation-free: __device__ globals)
__device__ float g_q [BATCH*NHEADS*SEQ*DHEAD];   // [B,H,L,dh]
__device__ float g_k [BATCH*NHEADS*SEQ*DHEAD];
__device__ float g_v [BATCH*NHEADS*SEQ*DHEAD];
__device__ float g_ao[MROWS*DMODEL];             // [B*L, D]

__device__ __forceinline__ uint32_t to_tf32(float f) {
    uint32_t r;
    asm("cvt.rna.tf32.f32 %0, %1;" : "=r"(r) : "f"(f));
    return r;
}
__device__ __forceinline__ float tf32f(float f) {
    return __uint_as_float(to_tf32(f));
}

#define LDSM4(r0,r1,r2,r3,addr) \
    asm volatile("ldmatrix.sync.aligned.m8n8.x4.shared.b16 {%0,%1,%2,%3}, [%4];" \
        : "=r"(r0),"=r"(r1),"=r"(r2),"=r"(r3) : "r"(addr))

#define MMA_TF32(c,a,b0,b1) \
    asm volatile("mma.sync.aligned.m16n8k8.row.col.f32.tf32.tf32.f32 " \
        "{%0,%1,%2,%3},{%4,%5,%6,%7},{%8,%9},{%0,%1,%2,%3};" \
        : "+f"(c[0]),"+f"(c[1]),"+f"(c[2]),"+f"(c[3]) \
        : "r"(a[0]),"r"(a[1]),"r"(a[2]),"r"(a[3]),"r"(b0),"r"(b1))

// ---------------------------------------------------------------------------
// tf32 GEMM core: C = A @ W^T.  A:[M,K] rm, W:[N,K] rm.
// CTA tile 128x128x32, 128 threads (4 warps, 2x2), warp tile 64x64.
// Double-buffered smem (2 stages), LDG prefetch -> cvt -> STS.
// Dynamic smem: 2 stages x (As[128*36] + Ws[128*36]) = 73728 B.
// ---------------------------------------------------------------------------
#define GSTAGE 4608                  // floats per tile (128*36)
#define GEMM_SMEM_BYTES (4*GSTAGE*4) // 73728

template<int PERMUTE>
__device__ __forceinline__ void gemm_core(
    const float* __restrict__ A, const float* __restrict__ W,
    float* __restrict__ C, float* sm)
{
    const int K = DMODEL;
    const int tid  = threadIdx.x;
    const int lane = tid & 31;
    const int wid  = tid >> 5;         // 0..3
    const int m0 = blockIdx.y * 128;
    const int n0 = blockIdx.x * 128;
    const int wm = (wid & 1) * 64;
    const int wn = (wid >> 1) * 64;

    float c[4][8][4];
    #pragma unroll
    for (int i = 0; i < 4; i++)
        #pragma unroll
        for (int j = 0; j < 8; j++)
            #pragma unroll
            for (int r = 0; r < 4; r++) c[i][j][r] = 0.0f;

    uint32_t sm_b = (uint32_t)__cvta_generic_to_shared(sm);
    // stage s base (bytes): s * 2*GSTAGE*4 ; Ws offset = GSTAGE*4
    uint32_t a_addr[4], b_addr[4];
    #pragma unroll
    for (int i = 0; i < 4; i++)
        a_addr[i] = sm_b + ((wm + i*16 + (lane & 15)) * 36 + (lane >> 4) * 4) * 4;
    #pragma unroll
    for (int p = 0; p < 4; p++)
        b_addr[p] = sm_b + GSTAGE*4 +
            ((wn + p*16 + ((lane >> 4) & 1) * 8 + (lane & 7)) * 36
             + ((lane >> 3) & 1) * 4) * 4;

    const int lrow = tid >> 3;          // base row pattern (idx>>3 with idx=tid+it*128)
    const int lcg  = tid & 7;

    // Prologue: fill stage 0 for k0 = 0
    {
        #pragma unroll
        for (int it = 0; it < 8; it++) {
            int row = (tid + it*128) >> 3;
            float4 va = *reinterpret_cast<const float4*>(
                &A[(size_t)(m0 + row) * K + lcg * 4]);
            float* ad = &sm[row * 36 + lcg * 4];
            ad[0] = tf32f(va.x); ad[1] = tf32f(va.y);
            ad[2] = tf32f(va.z); ad[3] = tf32f(va.w);
            float4 vw = *reinterpret_cast<const float4*>(
                &W[(size_t)(n0 + row) * K + lcg * 4]);
            float* wd = &sm[GSTAGE + row * 36 + lcg * 4];
            wd[0] = tf32f(vw.x); wd[1] = tf32f(vw.y);
            wd[2] = tf32f(vw.z); wd[3] = tf32f(vw.w);
        }
    }
    __syncthreads();

    for (int k0 = 0; k0 < K; k0 += 32) {
        const int cur = (k0 >> 5) & 1;
        const int nxt = cur ^ 1;
        const bool has_next = (k0 + 32) < K;

        // Prefetch next K-slab into registers (latency hidden by MMA below)
        float4 ra[8], rw[8];
        if (has_next) {
            #pragma unroll
            for (int it = 0; it < 8; it++) {
                int row = (tid + it*128) >> 3;
                ra[it] = *reinterpret_cast<const float4*>(
                    &A[(size_t)(m0 + row) * K + k0 + 32 + lcg * 4]);
                rw[it] = *reinterpret_cast<const float4*>(
                    &W[(size_t)(n0 + row) * K + k0 + 32 + lcg * 4]);
            }
        }

        const uint32_t soff = (uint32_t)cur * (2*GSTAGE*4);
        #pragma unroll
        for (int s = 0; s < 4; s++) {
            uint32_t a[4][4], bb[4][4];
            #pragma unroll
            for (int i = 0; i < 4; i++)
                LDSM4(a[i][0], a[i][1], a[i][2], a[i][3], a_addr[i] + soff + s*32);
            #pragma unroll
            for (int p = 0; p < 4; p++)
                LDSM4(bb[p][0], bb[p][1], bb[p][2], bb[p][3], b_addr[p] + soff + s*32);
            #pragma unroll
            for (int i = 0; i < 4; i++)
                #pragma unroll
                for (int p = 0; p < 4; p++) {
                    MMA_TF32(c[i][2*p],   a[i], bb[p][0], bb[p][1]);
                    MMA_TF32(c[i][2*p+1], a[i], bb[p][2], bb[p][3]);
                }
        }

        if (has_next) {
            float* asd = sm + nxt * 2*GSTAGE;
            float* wsd = asd + GSTAGE;
            #pragma unroll
            for (int it = 0; it < 8; it++) {
                int row = (tid + it*128) >> 3;
                float* ad = &asd[row * 36 + lcg * 4];
                ad[0] = tf32f(ra[it].x); ad[1] = tf32f(ra[it].y);
                ad[2] = tf32f(ra[it].z); ad[3] = tf32f(ra[it].w);
                float* wd = &wsd[row * 36 + lcg * 4];
                wd[0] = tf32f(rw[it].x); wd[1] = tf32f(rw[it].y);
                wd[2] = tf32f(rw[it].z); wd[3] = tf32f(rw[it].w);
            }
        }
        __syncthreads();
    }

    // Epilogue
    const int g  = lane >> 2;
    const int tq = lane & 3;
    #pragma unroll
    for (int i = 0; i < 4; i++) {
        #pragma unroll
        for (int j = 0; j < 8; j++) {
            int col = n0 + wn + j*8 + tq*2;
            #pragma unroll
            for (int t = 0; t < 2; t++) {
                int row = m0 + wm + i*16 + g + t*8;
                float2 v = make_float2(c[i][j][2*t], c[i][j][2*t+1]);
                if (PERMUTE) {
                    int b = row >> 11, l = row & (SEQ - 1);
                    int h = col >> 6, d = col & 63;
                    *reinterpret_cast<float2*>(
                        &C[(((size_t)(b*NHEADS + h)) * SEQ + l) * DHEAD + d]) = v;
                } else {
                    *reinterpret_cast<float2*>(&C[(size_t)row * DMODEL + col]) = v;
                }
            }
        }
    }
}

__global__ void __launch_bounds__(128)
gemm_qkv_kernel(const float* __restrict__ x,
                const float* __restrict__ Wq, const float* __restrict__ Wk,
                const float* __restrict__ Wv,
                float* __restrict__ q, float* __restrict__ k,
                float* __restrict__ v)
{
    extern __shared__ float sm[];
    const int z = blockIdx.z;
    const float* W = (z == 0) ? Wq : (z == 1) ? Wk : Wv;
    float* C = (z == 0) ? q : (z == 1) ? k : v;
    gemm_core<1>(x, W, C, sm);
}

__global__ void __launch_bounds__(128)
gemm_o_kernel(const float* __restrict__ A, const float* __restrict__ W,
              float* __restrict__ C)
{
    extern __shared__ float sm[];
    gemm_core<0>(A, W, C, sm);
}

// ---------------------------------------------------------------------------
// Flash attention, tf32 mma. CTA = 128 queries x one (b,h), 128 threads,
// 4 warps, warp tile m32 x n64 (BK=64). Reverse q-block order for balance.
// Dyn smem: Qs[128][68], Ks[64][68], Vt[64][68], Ps[128][68] = 104448 B.
// ---------------------------------------------------------------------------
#define QS_OFF 0
#define KS_OFF 8704
#define VT_OFF 13056
#define PS_OFF 17408
#define ATTN_SMEM_FLOATS 26112
#define ATTN_SMEM_BYTES  (ATTN_SMEM_FLOATS*4)

__global__ void __launch_bounds__(128)
attn_tf32(const float* __restrict__ gq, const float* __restrict__ gk,
          const float* __restrict__ gv, float* __restrict__ ao)
{
    extern __shared__ float sm[];
    float* Qs = sm + QS_OFF;
    float* Ks = sm + KS_OFF;
    float* Vt = sm + VT_OFF;
    float* Ps = sm + PS_OFF;

    const int tid  = threadIdx.x;
    const int lane = tid & 31;
    const int wid  = tid >> 5;                    // 0..3, owns 32 q rows
    const int bh = blockIdx.y;
    const int q0 = ((int)gridDim.x - 1 - (int)blockIdx.x) * 128;  // heavy first
    const float scale = 0.125f;

    // Load + scale + tf32 Q block: 128x64 = 2048 float4, 16 per thread
    {
        const float4* qbase = reinterpret_cast<const float4*>(
            gq + ((size_t)bh * SEQ + q0) * DHEAD);
        #pragma unroll
        for (int it = 0; it < 16; it++) {
            int idx = tid + it * 128;
            int row = idx >> 4, cg = idx & 15;
            float4 v = qbase[idx];
            float* d = &Qs[row * 68 + cg * 4];
            d[0] = tf32f(v.x * scale); d[1] = tf32f(v.y * scale);
            d[2] = tf32f(v.z * scale); d[3] = tf32f(v.w * scale);
        }
    }

    uint32_t qs_b = (uint32_t)__cvta_generic_to_shared(Qs);
    uint32_t ks_b = (uint32_t)__cvta_generic_to_shared(Ks);
    uint32_t vt_b = (uint32_t)__cvta_generic_to_shared(Vt);
    uint32_t ps_b = (uint32_t)__cvta_generic_to_shared(Ps);
    uint32_t qa_addr[2], pa_addr[2];
    #pragma unroll
    for (int mi = 0; mi < 2; mi++) {
        uint32_t roff = ((wid*32 + mi*16 + (lane & 15)) * 68 + (lane >> 4) * 4) * 4;
        qa_addr[mi] = qs_b + roff;
        pa_addr[mi] = ps_b + roff;
    }
    uint32_t kb_addr[4], vb_addr[4];
    #pragma unroll
    for (int p = 0; p < 4; p++) {
        uint32_t roff = ((p*16 + ((lane >> 4) & 1) * 8 + (lane & 7)) * 68
                        + ((lane >> 3) & 1) * 4) * 4;
        kb_addr[p] = ks_b + roff;
        vb_addr[p] = vt_b + roff;
    }

    float m_i[2][2] = {{-1e30f, -1e30f}, {-1e30f, -1e30f}};
    float l_i[2][2] = {{0.0f, 0.0f}, {0.0f, 0.0f}};
    float o[2][8][4];
    #pragma unroll
    for (int mi = 0; mi < 2; mi++)
        #pragma unroll
        for (int j = 0; j < 8; j++)
            #pragma unroll
            for (int r = 0; r < 4; r++) o[mi][j][r] = 0.0f;

    const int g  = lane >> 2;
    const int tq = lane & 3;

    const int nkb = (q0 + 128) / 64;
    for (int kb = 0; kb < nkb; kb++) {
        const int k0 = kb * 64;
        __syncthreads();   // protect K/V smem reuse (and Q load on iter 0)

        // Load K [64][64] and V transposed into Vt[d][key]: 1024 f4 each
        {
            const float4* kbase = reinterpret_cast<const float4*>(
                gk + ((size_t)bh * SEQ + k0) * DHEAD);
            const float4* vbase = reinterpret_cast<const float4*>(
                gv + ((size_t)bh * SEQ + k0) * DHEAD);
            #pragma unroll
            for (int it = 0; it < 8; it++) {
                int idx = tid + it * 128;     // 0..1023
                {
                    int row = idx >> 4, cg = idx & 15;
                    float4 v = kbase[idx];
                    float* d = &Ks[row * 68 + cg * 4];
                    d[0] = tf32f(v.x); d[1] = tf32f(v.y);
                    d[2] = tf32f(v.z); d[3] = tf32f(v.w);
                }
                {
                    int r = idx & 63, cg = idx >> 6;   // 0..15
                    float4 v = vbase[r * 16 + cg];
                    Vt[(cg*4+0) * 68 + r] = tf32f(v.x);
                    Vt[(cg*4+1) * 68 + r] = tf32f(v.y);
                    Vt[(cg*4+2) * 68 + r] = tf32f(v.z);
                    Vt[(cg*4+3) * 68 + r] = tf32f(v.w);
                }
            }
        }
        __syncthreads();

        // S = Q @ K^T : warp m32 x n64 x k64
        float sf[2][8][4];
        #pragma unroll
        for (int mi = 0; mi < 2; mi++)
            #pragma unroll
            for (int j = 0; j < 8; j++)
                #pragma unroll
                for (int r = 0; r < 4; r++) sf[mi][j][r] = 0.0f;

        #pragma unroll
        for (int s = 0; s < 8; s++) {
            uint32_t a[2][4], bb[4][4];
            #pragma unroll
            for (int mi = 0; mi < 2; mi++)
                LDSM4(a[mi][0], a[mi][1], a[mi][2], a[mi][3], qa_addr[mi] + s*32);
            #pragma unroll
            for (int p = 0; p < 4; p++)
                LDSM4(bb[p][0], bb[p][1], bb[p][2], bb[p][3], kb_addr[p] + s*32);
            #pragma unroll
            for (int mi = 0; mi < 2; mi++)
                #pragma unroll
                for (int p = 0; p < 4; p++) {
                    MMA_TF32(sf[mi][2*p],   a[mi], bb[p][0], bb[p][1]);
                    MMA_TF32(sf[mi][2*p+1], a[mi], bb[p][2], bb[p][3]);
                }
        }

        // Causal mask (only near diagonal)
        if (k0 + 63 > q0 + wid*32) {
            #pragma unroll
            for (int mi = 0; mi < 2; mi++)
                #pragma unroll
                for (int t = 0; t < 2; t++) {
                    int qg = q0 + wid*32 + mi*16 + g + t*8;
                    #pragma unroll
                    for (int j = 0; j < 8; j++) {
                        int kg = k0 + j*8 + tq*2;
                        if (kg   > qg) sf[mi][j][2*t]   = -1e30f;
                        if (kg+1 > qg) sf[mi][j][2*t+1] = -1e30f;
                    }
                }
        }

        // Online softmax; write P (tf32) to warp-private Ps rows
        #pragma unroll
        for (int mi = 0; mi < 2; mi++)
            #pragma unroll
            for (int t = 0; t < 2; t++) {
                float mx = -1e30f;
                #pragma unroll
                for (int j = 0; j < 8; j++)
                    mx = fmaxf(mx, fmaxf(sf[mi][j][2*t], sf[mi][j][2*t+1]));
                mx = fmaxf(mx, __shfl_xor_sync(0xffffffffu, mx, 1));
                mx = fmaxf(mx, __shfl_xor_sync(0xffffffffu, mx, 2));
                float newm = fmaxf(m_i[mi][t], mx);
                float corr = __expf(m_i[mi][t] - newm);
                float rs = 0.0f;
                int prow = (wid*32 + mi*16 + g + t*8) * 68 + tq*2;
                #pragma unroll
                for (int j = 0; j < 8; j++) {
                    float p0 = __expf(sf[mi][j][2*t]   - newm);
                    float p1 = __expf(sf[mi][j][2*t+1] - newm);
                    rs += p0 + p1;
                    *reinterpret_cast<float2*>(&Ps[prow + j*8]) =
                        make_float2(tf32f(p0), tf32f(p1));
                }
                rs += __shfl_xor_sync(0xffffffffu, rs, 1);
                rs += __shfl_xor_sync(0xffffffffu, rs, 2);
                l_i[mi][t] = l_i[mi][t] * corr + rs;
                m_i[mi][t] = newm;
                #pragma unroll
                for (int j = 0; j < 8; j++) {
                    o[mi][j][2*t]   *= corr;
                    o[mi][j][2*t+1] *= corr;
                }
            }
        __syncwarp();

        // O += P @ V : warp m32(q) x n64(d) x k64(keys)
        #pragma unroll
        for (int s = 0; s < 8; s++) {
            uint32_t a[2][4], bb[4][4];
            #pragma unroll
            for (int mi = 0; mi < 2; mi++)
                LDSM4(a[mi][0], a[mi][1], a[mi][2], a[mi][3], pa_addr[mi] + s*32);
            #pragma unroll
            for (int p = 0; p < 4; p++)
                LDSM4(bb[p][0], bb[p][1], bb[p][2], bb[p][3], vb_addr[p] + s*32);
            #pragma unroll
            for (int mi = 0; mi < 2; mi++)
                #pragma unroll
                for (int p = 0; p < 4; p++) {
                    MMA_TF32(o[mi][2*p],   a[mi], bb[p][0], bb[p][1]);
                    MMA_TF32(o[mi][2*p+1], a[mi], bb[p][2], bb[p][3]);
                }
        }
    }

    // Normalize and write to [B*L, D] (col = h*64 + d)
    const int b = bh >> 4;
    const int h = bh & 15;
    #pragma unroll
    for (int mi = 0; mi < 2; mi++)
        #pragma unroll
        for (int t = 0; t < 2; t++) {
            float inv = 1.0f / l_i[mi][t];
            int row = q0 + wid*32 + mi*16 + g + t*8;
            float* dst = ao + ((size_t)(b * SEQ + row)) * DMODEL + h * DHEAD + tq*2;
            #pragma unroll
            for (int j = 0; j < 8; j++)
                *reinterpret_cast<float2*>(dst + j*8) =
                    make_float2(o[mi][j][2*t] * inv, o[mi][j][2*t+1] * inv);
        }
}

// ---------------------------------------------------------------------------
extern "C" void kernel_launch(void* const* d_in, const int* in_sizes, int n_in,
                              void* d_out, int out_size)
{
    const float* x  = (const float*)d_in[0];
    const float* Wq = (const float*)d_in[1];
    const float* Wk = (const float*)d_in[2];
    const float* Wv = (const float*)d_in[3];
    const float* Wo = (const float*)d_in[4];
    float* out = (float*)d_out;

    float *qp, *kp, *vp, *aop;
    cudaGetSymbolAddress((void**)&qp,  g_q);
    cudaGetSymbolAddress((void**)&kp,  g_k);
    cudaGetSymbolAddress((void**)&vp,  g_v);
    cudaGetSymbolAddress((void**)&aop, g_ao);

    static int configured = 0;
    cudaFuncSetAttribute(gemm_qkv_kernel,
        cudaFuncAttributeMaxDynamicSharedMemorySize, GEMM_SMEM_BYTES);
    cudaFuncSetAttribute(gemm_o_kernel,
        cudaFuncAttributeMaxDynamicSharedMemorySize, GEMM_SMEM_BYTES);
    cudaFuncSetAttribute(attn_tf32,
        cudaFuncAttributeMaxDynamicSharedMemorySize, ATTN_SMEM_BYTES);
    (void)configured;

    dim3 qkv_grid(DMODEL / 128, MROWS / 128, 3);   // (8, 64, 3)
    gemm_qkv_kernel<<<qkv_grid, 128, GEMM_SMEM_BYTES>>>(x, Wq, Wk, Wv, qp, kp, vp);

    dim3 attn_grid(SEQ / 128, BATCH * NHEADS);     // (16, 64)
    attn_tf32<<<attn_grid, 128, ATTN_SMEM_BYTES>>>(qp, kp, vp, aop);

    dim3 o_grid(DMODEL / 128, MROWS / 128);        // (8, 64)
    gemm_o_kernel<<<o_grid, 128, GEMM_SMEM_BYTES>>>(aop, Wo, out);
}